// round 5
// baseline (speedup 1.0000x reference)
#include <cuda_runtime.h>

#define DM   2048   // d_model
#define DS   16     // d_state
#define NB   8      // batch
#define LQ   512    // seq
#define NC   16     // chunks
#define LC   32     // chunk length (NC*LC == LQ)
#define HS   8      // states per thread (half of DS)

#define BDIM 256
#define NBLK 740                      // 148 SMs x 5 blocks (occupancy-guaranteed)
#define NTHREADS (NBLK * BDIM)        // 189440

#define N_PRE  (DM * DS)              // 32768
#define N_A    (2 * NC * NB * DM)     // 524288
#define N_B    (2 * NB * DM * HS)     // 262144
#define SLAB   (NB * DM * HS)         // 131072 floats per (half,c) slab

// ---- scratch (no allocations allowed) ----
__device__ float g_dA  [DM * DS];
__device__ float g_cb  [DM * DS];
__device__ float g_dAL [DM * DS];
__device__ float g_end [2 * NC * SLAB];
__device__ float g_init[2 * NC * SLAB];
__device__ unsigned g_cnt;            // monotonic grid-barrier ticket counter

// ---- packed f32x2 helpers ----
__device__ __forceinline__ unsigned long long pk(float lo, float hi) {
    unsigned long long r;
    asm("mov.b64 %0, {%1, %2};" : "=l"(r) : "f"(lo), "f"(hi));
    return r;
}
__device__ __forceinline__ void upk(unsigned long long v, float& lo, float& hi) {
    asm("mov.b64 {%0, %1}, %2;" : "=f"(lo), "=f"(hi) : "l"(v));
}
__device__ __forceinline__ unsigned long long fma2(unsigned long long a,
                                                   unsigned long long b,
                                                   unsigned long long c) {
    unsigned long long r;
    asm("fma.rn.f32x2 %0, %1, %2, %3;" : "=l"(r) : "l"(a), "l"(b), "l"(c));
    return r;
}
__device__ __forceinline__ unsigned long long mul2(unsigned long long a,
                                                   unsigned long long b) {
    unsigned long long r;
    asm("mul.rn.f32x2 %0, %1, %2;" : "=l"(r) : "l"(a), "l"(b));
    return r;
}
__device__ __forceinline__ unsigned long long add2(unsigned long long a,
                                                   unsigned long long b) {
    unsigned long long r;
    asm("add.rn.f32x2 %0, %1, %2;" : "=l"(r) : "l"(a), "l"(b));
    return r;
}

// ---- replay-safe grid barrier (ticket/round; all NBLK blocks co-resident) ----
__device__ __forceinline__ void grid_barrier() {
    __syncthreads();
    if (threadIdx.x == 0) {
        __threadfence();
        unsigned t = atomicAdd(&g_cnt, 1u);
        unsigned target = (t / NBLK + 1u) * NBLK;
        volatile unsigned* p = &g_cnt;
        while (*p < target) { }
        __threadfence();
    }
    __syncthreads();
}

__global__ void __launch_bounds__(BDIM, 5)
k_fused(const float* __restrict__ x,
        const float* __restrict__ A_log,
        const float* __restrict__ Bm,
        const float* __restrict__ Cm,
        const float* __restrict__ log_dt,
        float* __restrict__ y) {
    const int gtid = blockIdx.x * BDIM + threadIdx.x;

    // ---- phase P: parameter precompute ----
    if (gtid < N_PRE) {
        int i = gtid;
        int d = i >> 4;
        float dt = expf(log_dt[d]);          // DT_SCALE = 1
        float A  = expf(A_log[i]);
        float u  = dt * A;
        g_dA[i]  = expf(u);
        g_dAL[i] = expf((float)LC * u);
        g_cb[i]  = Cm[i] * (dt * Bm[i]);
    }
    grid_barrier();

    // ---- phase A: local chunk end states (zero init), split-state ----
    for (int it = gtid; it < N_A; it += NTHREADS) {
        int half = (it >> 4) & 1;
        int pi   = ((it >> 5) << 4) | (it & 15);
        int d = pi & (DM - 1);
        int b = (pi >> 11) & (NB - 1);
        int c = pi >> 14;

        unsigned long long dA2[4];
        const float4* pa = (const float4*)(g_dA + (d << 4) + half * HS);
#pragma unroll
        for (int k = 0; k < 2; k++) {
            float4 v = pa[k];
            dA2[2 * k]     = pk(v.x, v.y);
            dA2[2 * k + 1] = pk(v.z, v.w);
        }

        unsigned long long p2[4];
#pragma unroll
        for (int k = 0; k < 4; k++) p2[k] = 0ull;

        const float* xp = x + (size_t)(b * LQ + c * LC) * DM + d;
#pragma unroll 8
        for (int t = 0; t < LC; t++) {
            float xt = xp[(size_t)t * DM];
            unsigned long long xx = pk(xt, xt);
#pragma unroll
            for (int k = 0; k < 4; k++) p2[k] = fma2(dA2[k], p2[k], xx);
        }

        size_t e_idx = ((size_t)(half * NC + c) * NB + b) * DM * HS + (size_t)d * HS;
        float4* pe = (float4*)(g_end + e_idx);
#pragma unroll
        for (int k = 0; k < 2; k++) {
            float a0, a1, a2, a3;
            upk(p2[2 * k], a0, a1);
            upk(p2[2 * k + 1], a2, a3);
            pe[k] = make_float4(a0, a1, a2, a3);
        }
    }
    grid_barrier();

    // ---- phase B: inter-chunk scan over NC chunks ----
    for (int it = gtid; it < N_B; it += NTHREADS) {
        int j    = it & (HS - 1);
        int d    = (it >> 3) & (DM - 1);
        int b    = (it >> 14) & (NB - 1);
        int half = it >> 17;
        float aL = g_dAL[(d << 4) | (half * HS + j)];

        size_t base = ((size_t)(half * NC) * NB + b) * DM * HS + (size_t)d * HS + j;
        float h = 0.0f;
#pragma unroll
        for (int c = 1; c < NC; c++) {
            h = fmaf(aL, h, g_end[base + (size_t)(c - 1) * SLAB]);
            g_init[base + (size_t)c * SLAB] = h;
        }
    }
    grid_barrier();

    // ---- phase C: full scan with init + output dot ----
    for (int it = gtid; it < N_A; it += NTHREADS) {
        int half = (it >> 4) & 1;
        int pi   = ((it >> 5) << 4) | (it & 15);
        int d = pi & (DM - 1);
        int b = (pi >> 11) & (NB - 1);
        int c = pi >> 14;

        unsigned long long dA2[4], cb2[4];
        const float4* pa = (const float4*)(g_dA + (d << 4) + half * HS);
        const float4* pc = (const float4*)(g_cb + (d << 4) + half * HS);
#pragma unroll
        for (int k = 0; k < 2; k++) {
            float4 va = pa[k];
            dA2[2 * k]     = pk(va.x, va.y);
            dA2[2 * k + 1] = pk(va.z, va.w);
            float4 vc = pc[k];
            cb2[2 * k]     = pk(vc.x, vc.y);
            cb2[2 * k + 1] = pk(vc.z, vc.w);
        }

        unsigned long long p2[4];
        if (c == 0) {
#pragma unroll
            for (int k = 0; k < 4; k++) p2[k] = 0ull;
        } else {
            size_t e_idx = ((size_t)(half * NC + c) * NB + b) * DM * HS + (size_t)d * HS;
            const float4* pi4 = (const float4*)(g_init + e_idx);
#pragma unroll
            for (int k = 0; k < 2; k++) {
                float4 v = pi4[k];
                p2[2 * k]     = pk(v.x, v.y);
                p2[2 * k + 1] = pk(v.z, v.w);
            }
        }

        size_t off = (size_t)(b * LQ + c * LC) * DM + d;
        const float* xp = x + off;
        float*       yp = y + off;

#pragma unroll 8
        for (int t = 0; t < LC; t++) {
            float xt = xp[(size_t)t * DM];
            unsigned long long xx = pk(xt, xt);
#pragma unroll
            for (int k = 0; k < 4; k++) p2[k] = fma2(dA2[k], p2[k], xx);

            unsigned long long acc0 = mul2(cb2[0], p2[0]);
            unsigned long long acc1 = mul2(cb2[1], p2[1]);
            acc0 = fma2(cb2[2], p2[2], acc0);
            acc1 = fma2(cb2[3], p2[3], acc1);
            unsigned long long acc = add2(acc0, acc1);
            float s0, s1;
            upk(acc, s0, s1);
            float s = s0 + s1;
            s += __shfl_xor_sync(0xffffffffu, s, 16);
            if (half == 0) yp[(size_t)t * DM] = s;
        }
    }
}

extern "C" void kernel_launch(void* const* d_in, const int* in_sizes, int n_in,
                              void* d_out, int out_size) {
    const float* x      = (const float*)d_in[0];
    const float* A_log  = (const float*)d_in[1];
    const float* B      = (const float*)d_in[2];
    const float* C      = (const float*)d_in[3];
    const float* log_dt = (const float*)d_in[4];
    float* y = (float*)d_out;

    k_fused<<<NBLK, BDIM>>>(x, A_log, B, C, log_dt, y);
}

// round 6
// speedup vs baseline: 1.4922x; 1.4922x over previous
#include <cuda_runtime.h>

#define DM   2048   // d_model
#define DS   16     // d_state
#define NB   8      // batch
#define LQ   512    // seq
#define QS   4      // states per thread (quarter of DS)

#define BDIM 128
#define NTH  (4 * NB * DM)   // 65536 threads total

// ---- precomputed params (no allocations allowed) ----
__device__ float g_dA[DM * DS];   // exp(dt*A)
__device__ float g_cb[DM * DS];   // C * dt * B

// ---- packed f32x2 helpers ----
__device__ __forceinline__ unsigned long long pk(float lo, float hi) {
    unsigned long long r;
    asm("mov.b64 %0, {%1, %2};" : "=l"(r) : "f"(lo), "f"(hi));
    return r;
}
__device__ __forceinline__ void upk(unsigned long long v, float& lo, float& hi) {
    asm("mov.b64 {%0, %1}, %2;" : "=f"(lo), "=f"(hi) : "l"(v));
}
__device__ __forceinline__ unsigned long long fma2(unsigned long long a,
                                                   unsigned long long b,
                                                   unsigned long long c) {
    unsigned long long r;
    asm("fma.rn.f32x2 %0, %1, %2, %3;" : "=l"(r) : "l"(a), "l"(b), "l"(c));
    return r;
}
__device__ __forceinline__ unsigned long long mul2(unsigned long long a,
                                                   unsigned long long b) {
    unsigned long long r;
    asm("mul.rn.f32x2 %0, %1, %2;" : "=l"(r) : "l"(a), "l"(b));
    return r;
}

// ---- kernel 0: parameter precompute (one-shot, tiny) ----
__global__ void k_pre(const float* __restrict__ A_log,
                      const float* __restrict__ Bm,
                      const float* __restrict__ Cm,
                      const float* __restrict__ log_dt) {
    int i = blockIdx.x * blockDim.x + threadIdx.x;
    if (i >= DM * DS) return;
    int d = i >> 4;
    float dt = expf(log_dt[d]);          // DT_SCALE = 1
    float A  = expf(A_log[i]);
    g_dA[i] = expf(dt * A);
    g_cb[i] = Cm[i] * (dt * Bm[i]);
}

// ---- monolithic scan: each thread owns 4 states of one (b,d); 4 threads
//      per (b,d) live in lanes {s, s+8, s+16, s+24}; butterfly-reduce y ----
__global__ void __launch_bounds__(BDIM)
k_mono(const float* __restrict__ x, float* __restrict__ y) {
    int gtid = blockIdx.x * BDIM + threadIdx.x;     // [0, 65536)
    int lane = threadIdx.x & 31;
    int q    = lane >> 3;                           // quarter 0..3
    int pe   = ((gtid >> 5) << 3) | (lane & 7);     // (b,d) index, [0, 16384)
    int d = pe & (DM - 1);
    int b = pe >> 11;

    // this thread's 4 states: n in [q*4, q*4+4)
    unsigned long long dA2[2], cb2[2];
    {
        float4 va = *(const float4*)(g_dA + (d << 4) + q * QS);
        dA2[0] = pk(va.x, va.y);
        dA2[1] = pk(va.z, va.w);
        float4 vc = *(const float4*)(g_cb + (d << 4) + q * QS);
        cb2[0] = pk(vc.x, vc.y);
        cb2[1] = pk(vc.z, vc.w);
    }

    unsigned long long p0 = 0ull, p1 = 0ull;

    const float* xp = x + (size_t)b * LQ * DM + d;
    float*       yp = y + (size_t)b * LQ * DM + d;

#pragma unroll 16
    for (int t = 0; t < LQ; t++) {
        float xt = __ldg(xp + (size_t)t * DM);
        unsigned long long xx = pk(xt, xt);

        p0 = fma2(dA2[0], p0, xx);
        p1 = fma2(dA2[1], p1, xx);

        unsigned long long acc = mul2(cb2[0], p0);
        acc = fma2(cb2[1], p1, acc);
        float s0, s1;
        upk(acc, s0, s1);
        float s = s0 + s1;
        s += __shfl_xor_sync(0xffffffffu, s, 8);
        s += __shfl_xor_sync(0xffffffffu, s, 16);
        if (q == 0) yp[(size_t)t * DM] = s;
    }
}

extern "C" void kernel_launch(void* const* d_in, const int* in_sizes, int n_in,
                              void* d_out, int out_size) {
    const float* x      = (const float*)d_in[0];
    const float* A_log  = (const float*)d_in[1];
    const float* B      = (const float*)d_in[2];
    const float* C      = (const float*)d_in[3];
    const float* log_dt = (const float*)d_in[4];
    float* y = (float*)d_out;

    k_pre<<<(DM * DS + 255) / 256, 256>>>(A_log, B, C, log_dt);
    k_mono<<<NTH / BDIM, BDIM>>>(x, y);
}

// round 7
// speedup vs baseline: 1.5906x; 1.0659x over previous
#include <cuda_runtime.h>

#define DM   2048   // d_model
#define DS   16     // d_state
#define NB   8      // batch
#define LQ   512    // seq
#define NC   8      // chunks
#define LC   64     // chunk length (NC*LC == LQ)

#define BDIM 128

typedef unsigned long long ull;

// ---- precomputed params + chunk end-state scratch ----
__device__ float g_dA [DM * DS];          // exp(dt*A)
__device__ float g_dAL[DM * DS];          // exp(LC*dt*A) = dA^LC
__device__ float g_cb [DM * DS];          // C * dt * B
__device__ float g_end[(NC - 1) * NB * DM * DS];  // end state of chunks 0..NC-2

// ---- packed f32x2 helpers ----
__device__ __forceinline__ ull pk(float lo, float hi) {
    ull r;
    asm("mov.b64 %0, {%1, %2};" : "=l"(r) : "f"(lo), "f"(hi));
    return r;
}
__device__ __forceinline__ void upk(ull v, float& lo, float& hi) {
    asm("mov.b64 {%0, %1}, %2;" : "=f"(lo), "=f"(hi) : "l"(v));
}
__device__ __forceinline__ ull fma2(ull a, ull b, ull c) {
    ull r;
    asm("fma.rn.f32x2 %0, %1, %2, %3;" : "=l"(r) : "l"(a), "l"(b), "l"(c));
    return r;
}
__device__ __forceinline__ ull mul2(ull a, ull b) {
    ull r;
    asm("mul.rn.f32x2 %0, %1, %2;" : "=l"(r) : "l"(a), "l"(b));
    return r;
}
__device__ __forceinline__ ull add2(ull a, ull b) {
    ull r;
    asm("add.rn.f32x2 %0, %1, %2;" : "=l"(r) : "l"(a), "l"(b));
    return r;
}

// load 16 floats (param row) as 8 f32x2
__device__ __forceinline__ void ld_row(const float* p, ull* v) {
#pragma unroll
    for (int k = 0; k < 4; k++) {
        float4 f = ((const float4*)p)[k];
        v[2 * k]     = pk(f.x, f.y);
        v[2 * k + 1] = pk(f.z, f.w);
    }
}

// ---- kernel 0: parameter precompute (one-shot, tiny) ----
__global__ void k_pre(const float* __restrict__ A_log,
                      const float* __restrict__ Bm,
                      const float* __restrict__ Cm,
                      const float* __restrict__ log_dt) {
    int i = blockIdx.x * blockDim.x + threadIdx.x;
    if (i >= DM * DS) return;
    int d = i >> 4;
    float dt = expf(log_dt[d]);          // DT_SCALE = 1
    float A  = expf(A_log[i]);
    float u  = dt * A;
    g_dA[i]  = expf(u);
    g_dAL[i] = expf((float)LC * u);
    g_cb[i]  = Cm[i] * (dt * Bm[i]);
}

// ---- phase A: end states of chunks 0..NC-2, full state per thread ----
__global__ void __launch_bounds__(BDIM)
k_A(const float* __restrict__ x) {
    int idx = blockIdx.x * BDIM + threadIdx.x;   // (NC-1)*NB*DM = 114688
    int d = idx & (DM - 1);
    int b = (idx >> 11) & (NB - 1);
    int c = idx >> 14;                           // 0..NC-2

    ull dA2[8];
    ld_row(g_dA + (d << 4), dA2);

    ull p2[8];
#pragma unroll
    for (int k = 0; k < 8; k++) p2[k] = 0ull;

    const float* xp = x + (size_t)(b * LQ + c * LC) * DM + d;
#pragma unroll 8
    for (int t = 0; t < LC; t++) {
        float xt = xp[(size_t)t * DM];
        ull xx = pk(xt, xt);
#pragma unroll
        for (int k = 0; k < 8; k++) p2[k] = fma2(dA2[k], p2[k], xx);
    }

    float4* pe = (float4*)(g_end + ((size_t)idx << 4));
#pragma unroll
    for (int k = 0; k < 4; k++) {
        float a0, a1, a2, a3;
        upk(p2[2 * k], a0, a1);
        upk(p2[2 * k + 1], a2, a3);
        pe[k] = make_float4(a0, a1, a2, a3);
    }
}

// ---- phase C: inline chunk-init reconstruction + scan + output dot ----
__global__ void __launch_bounds__(BDIM)
k_C(const float* __restrict__ x, float* __restrict__ y) {
    int idx = blockIdx.x * BDIM + threadIdx.x;   // NC*NB*DM = 131072
    int d = idx & (DM - 1);
    int b = (idx >> 11) & (NB - 1);
    int c = idx >> 14;                           // 0..NC-1

    ull dA2[8], cb2[8];
    ld_row(g_dA + (d << 4), dA2);
    ld_row(g_cb + (d << 4), cb2);

    ull p2[8];
#pragma unroll
    for (int k = 0; k < 8; k++) p2[k] = 0ull;

    // init = scan of prior chunk end-states with dA^LC (c uniform per warp)
    if (c > 0) {
        ull dAL2[8];
        ld_row(g_dAL + (d << 4), dAL2);
        int bd16 = ((b << 11) | d) << 4;
        for (int cc = 0; cc < c; cc++) {
            const float4* pe = (const float4*)(g_end + (size_t)(cc << 18) + bd16);
#pragma unroll
            for (int k = 0; k < 4; k++) {
                float4 v = pe[k];
                p2[2 * k]     = fma2(dAL2[2 * k],     p2[2 * k],     pk(v.x, v.y));
                p2[2 * k + 1] = fma2(dAL2[2 * k + 1], p2[2 * k + 1], pk(v.z, v.w));
            }
        }
    }

    size_t off = (size_t)(b * LQ + c * LC) * DM + d;
    const float* xp = x + off;
    float*       yp = y + off;

#pragma unroll 8
    for (int t = 0; t < LC; t++) {
        float xt = xp[(size_t)t * DM];
        ull xx = pk(xt, xt);
#pragma unroll
        for (int k = 0; k < 8; k++) p2[k] = fma2(dA2[k], p2[k], xx);

        ull acc0 = mul2(cb2[0], p2[0]);
        ull acc1 = mul2(cb2[1], p2[1]);
#pragma unroll
        for (int k = 2; k < 8; k += 2) {
            acc0 = fma2(cb2[k],     p2[k],     acc0);
            acc1 = fma2(cb2[k + 1], p2[k + 1], acc1);
        }
        ull acc = add2(acc0, acc1);
        float s0, s1;
        upk(acc, s0, s1);
        yp[(size_t)t * DM] = s0 + s1;
    }
}

extern "C" void kernel_launch(void* const* d_in, const int* in_sizes, int n_in,
                              void* d_out, int out_size) {
    const float* x      = (const float*)d_in[0];
    const float* A_log  = (const float*)d_in[1];
    const float* B      = (const float*)d_in[2];
    const float* C      = (const float*)d_in[3];
    const float* log_dt = (const float*)d_in[4];
    float* y = (float*)d_out;

    k_pre<<<(DM * DS + 255) / 256, 256>>>(A_log, B, C, log_dt);
    k_A<<<((NC - 1) * NB * DM) / BDIM, BDIM>>>(x);
    k_C<<<(NC * NB * DM) / BDIM, BDIM>>>(x, y);
}